// round 12
// baseline (speedup 1.0000x reference)
#include <cuda_runtime.h>
#include <cuda_bf16.h>
#include <cstdint>

// Problem: out[v][g][u][d] = W[GE[v][g] % 3][d] + b[d]
//   V=512, G=4, D=64, out shape [V,G,V,D] fp32 = 256 MB (pure write-bound).
//
// GE is int32 on-device (JAX x64 disabled).
//
// R10: single uniform wave. 1024 CTAs x 256 threads (~6.9 CTAs/SM, all
// resident at t=0), each CTA writes exactly 2 consecutive (v,g) slabs
// (256 KB sequential). Same proven per-thread pattern as R4: each thread
// owns one float4 of the 64-float emb row and stores it to 16 u-rows per
// k-step (4KB contiguous per CTA-iteration), evict-first streaming.
// Removes R4's ragged 73%-full second wave + wave transition.

static constexpr int V = 512;
static constexpr int G = 4;
static constexpr int D = 64;
static constexpr int DQ = D / 4;          // 16 float4 per d-row
static constexpr int ROW_F4 = V * DQ;     // 8192 float4 per (v,g) slab
static constexpr int PAIRS_PER_CTA = 2;
static constexpr int NUM_CTAS = (V * G) / PAIRS_PER_CTA;   // 1024

__global__ __launch_bounds__(256, 8)
void gembedding_broadcast_kernel(const int* __restrict__ GE,
                                 const float* __restrict__ W,   // [3, 64]
                                 const float* __restrict__ b,   // [64]
                                 float4* __restrict__ out) {
    const int t  = threadIdx.x;
    const int dq = t & (DQ - 1);                 // which float4 of the d-row
    const int u0 = t >> 4;                       // 0..15 base u

    const float* brow = b + dq * 4;
    const float b0 = brow[0], b1 = brow[1], b2 = brow[2], b3 = brow[3];

    const int pair0 = blockIdx.x * PAIRS_PER_CTA;

    #pragma unroll
    for (int p = 0; p < PAIRS_PER_CTA; p++) {
        const int pair = pair0 + p;
        const int ge = GE[pair] % 3;             // values in [0,3)

        const float* wrow = W + ge * D + dq * 4;
        float4 val;
        val.x = wrow[0] + b0;
        val.y = wrow[1] + b1;
        val.z = wrow[2] + b2;
        val.w = wrow[3] + b3;

        float4* base = out + (size_t)pair * ROW_F4 + dq;
        // 512 u-rows, 16 per k-step -> 32 independent iterations.
        #pragma unroll
        for (int k = 0; k < 32; k++) {
            __stcs(&base[(size_t)(u0 + k * 16) * DQ], val);
        }
    }
}

extern "C" void kernel_launch(void* const* d_in, const int* in_sizes, int n_in,
                              void* d_out, int out_size) {
    const int*   GE = (const int*)d_in[0];     // [V, G, 1] int32
    const float* W  = (const float*)d_in[1];   // [3, D]
    const float* b  = (const float*)d_in[2];   // [D]
    float4* out = (float4*)d_out;

    gembedding_broadcast_kernel<<<NUM_CTAS, 256>>>(GE, W, b, out);
}

// round 13
// speedup vs baseline: 1.1490x; 1.1490x over previous
#include <cuda_runtime.h>
#include <cuda_bf16.h>
#include <cstdint>

// Problem: out[v][g][u][d] = W[GE[v][g] % 3][d] + b[d]
//   V=512, G=4, D=64, out shape [V,G,V,D] fp32 = 256 MB (pure write-bound).
//
// GE is int32 on-device (JAX x64 disabled).
//
// R12: fine-grained wave quantization. Steady-state dur_us is pinned at
// 268MB / DRAM-write-ceiling (~6.2 TB/s sustained incl. inter-replay
// drain); all saturating shapes plateau at ~43.5us. The one recoverable
// term is the ragged final wave: R4's 2048 CTAs ran 1.73 waves (86.5%
// time-avg utilization). Here: 8192 CTAs x 256 thr, each writing a
// quarter-slab (128 u-rows = 32KB), -> 6.9 waves, 98.8% utilization,
// same per-warp coalesced float4 evict-first store pattern.

static constexpr int V = 512;
static constexpr int G = 4;
static constexpr int D = 64;
static constexpr int DQ = D / 4;            // 16 float4 per d-row
static constexpr int ROW_F4 = V * DQ;       // 8192 float4 per (v,g) slab
static constexpr int CHUNKS_PER_PAIR = 4;   // quarter-slab per CTA
static constexpr int U_PER_CHUNK = V / CHUNKS_PER_PAIR;   // 128 u-rows
static constexpr int NUM_CTAS = V * G * CHUNKS_PER_PAIR;  // 8192

__global__ __launch_bounds__(256, 8)
void gembedding_broadcast_kernel(const int* __restrict__ GE,
                                 const float* __restrict__ W,   // [3, 64]
                                 const float* __restrict__ b,   // [64]
                                 float4* __restrict__ out) {
    const int blk   = blockIdx.x;                  // 0..8191
    const int pair  = blk >> 2;                    // v*G + g
    const int chunk = blk & 3;                     // which quarter of u-rows

    const int ge = GE[pair] % 3;                   // values in [0,3)

    const int t  = threadIdx.x;
    const int dq = t & (DQ - 1);                   // which float4 of the d-row
    const int u0 = chunk * U_PER_CHUNK + (t >> 4); // base u within our chunk

    const float* wrow = W + ge * D + dq * 4;
    const float* brow = b + dq * 4;
    float4 val;
    val.x = wrow[0] + brow[0];
    val.y = wrow[1] + brow[1];
    val.z = wrow[2] + brow[2];
    val.w = wrow[3] + brow[3];

    float4* base = out + (size_t)pair * ROW_F4 + dq;
    // 128 u-rows per chunk, 16 covered per k-step -> 8 independent stores.
    #pragma unroll
    for (int k = 0; k < U_PER_CHUNK / 16; k++) {
        __stcs(&base[(size_t)(u0 + k * 16) * DQ], val);
    }
}

extern "C" void kernel_launch(void* const* d_in, const int* in_sizes, int n_in,
                              void* d_out, int out_size) {
    const int*   GE = (const int*)d_in[0];     // [V, G, 1] int32
    const float* W  = (const float*)d_in[1];   // [3, D]
    const float* b  = (const float*)d_in[2];   // [D]
    float4* out = (float4*)d_out;

    gembedding_broadcast_kernel<<<NUM_CTAS, 256>>>(GE, W, b, out);
}

// round 15
// speedup vs baseline: 1.1889x; 1.0347x over previous
#include <cuda_runtime.h>
#include <cuda_bf16.h>
#include <cstdint>

// Problem: out[v][g][u][d] = W[GE[v][g] % 3][d] + b[d]
//   V=512, G=4, D=64, out shape [V,G,V,D] fp32 = 256 MB (pure write-bound).
//
// GE is int32 on-device (JAX x64 disabled).
//
// R13: continue the R12 granularity gradient (2048 CTAs @43.5us ->
// 8192 @41.0us). Now 16384 CTAs x 256 thr, each writing an eighth-slab
// (64 u-rows = 16KB): waves 6.9 -> 13.8 (tail fraction 13% -> 6%),
// flatter concurrency, same coalesced float4 evict-first pattern with
// 4 independent stores per thread.

static constexpr int V = 512;
static constexpr int G = 4;
static constexpr int D = 64;
static constexpr int DQ = D / 4;            // 16 float4 per d-row
static constexpr int ROW_F4 = V * DQ;       // 8192 float4 per (v,g) slab
static constexpr int CHUNKS_PER_PAIR = 8;   // eighth-slab per CTA
static constexpr int U_PER_CHUNK = V / CHUNKS_PER_PAIR;   // 64 u-rows
static constexpr int NUM_CTAS = V * G * CHUNKS_PER_PAIR;  // 16384

__global__ __launch_bounds__(256, 8)
void gembedding_broadcast_kernel(const int* __restrict__ GE,
                                 const float* __restrict__ W,   // [3, 64]
                                 const float* __restrict__ b,   // [64]
                                 float4* __restrict__ out) {
    const int blk   = blockIdx.x;                  // 0..16383
    const int pair  = blk >> 3;                    // v*G + g
    const int chunk = blk & 7;                     // which eighth of u-rows

    const int ge = GE[pair] % 3;                   // values in [0,3)

    const int t  = threadIdx.x;
    const int dq = t & (DQ - 1);                   // which float4 of the d-row
    const int u0 = chunk * U_PER_CHUNK + (t >> 4); // base u within our chunk

    const float* wrow = W + ge * D + dq * 4;
    const float* brow = b + dq * 4;
    float4 val;
    val.x = wrow[0] + brow[0];
    val.y = wrow[1] + brow[1];
    val.z = wrow[2] + brow[2];
    val.w = wrow[3] + brow[3];

    float4* base = out + (size_t)pair * ROW_F4 + dq;
    // 64 u-rows per chunk, 16 covered per k-step -> 4 independent stores.
    #pragma unroll
    for (int k = 0; k < U_PER_CHUNK / 16; k++) {
        __stcs(&base[(size_t)(u0 + k * 16) * DQ], val);
    }
}

extern "C" void kernel_launch(void* const* d_in, const int* in_sizes, int n_in,
                              void* d_out, int out_size) {
    const int*   GE = (const int*)d_in[0];     // [V, G, 1] int32
    const float* W  = (const float*)d_in[1];   // [3, D]
    const float* b  = (const float*)d_in[2];   // [D]
    float4* out = (float4*)d_out;

    gembedding_broadcast_kernel<<<NUM_CTAS, 256>>>(GE, W, b, out);
}

// round 16
// speedup vs baseline: 1.1976x; 1.0073x over previous
#include <cuda_runtime.h>
#include <cuda_bf16.h>
#include <cstdint>

// Problem: out[v][g][u][d] = W[GE[v][g] % 3][d] + b[d]
//   V=512, G=4, D=64, out shape [V,G,V,D] fp32 = 256 MB (pure write-bound).
//
// GE is int32 on-device (JAX x64 disabled).
//
// R15: bracket the granularity optimum (2048@43.5 -> 8192@41.0 ->
// 16384@39.6). Now 32768 CTAs x 256 thr, each writing a sixteenth-slab
// (32 u-rows = 8KB): ~27.7 waves, 3% tail fraction, 2 independent
// float4 evict-first stores per thread.

static constexpr int V = 512;
static constexpr int G = 4;
static constexpr int D = 64;
static constexpr int DQ = D / 4;             // 16 float4 per d-row
static constexpr int ROW_F4 = V * DQ;        // 8192 float4 per (v,g) slab
static constexpr int CHUNKS_PER_PAIR = 16;   // sixteenth-slab per CTA
static constexpr int U_PER_CHUNK = V / CHUNKS_PER_PAIR;   // 32 u-rows
static constexpr int NUM_CTAS = V * G * CHUNKS_PER_PAIR;  // 32768

__global__ __launch_bounds__(256, 8)
void gembedding_broadcast_kernel(const int* __restrict__ GE,
                                 const float* __restrict__ W,   // [3, 64]
                                 const float* __restrict__ b,   // [64]
                                 float4* __restrict__ out) {
    const int blk   = blockIdx.x;                  // 0..32767
    const int pair  = blk >> 4;                    // v*G + g
    const int chunk = blk & 15;                    // which 1/16 of u-rows

    const int ge = GE[pair] % 3;                   // values in [0,3)

    const int t  = threadIdx.x;
    const int dq = t & (DQ - 1);                   // which float4 of the d-row
    const int u0 = chunk * U_PER_CHUNK + (t >> 4); // base u within our chunk

    const float* wrow = W + ge * D + dq * 4;
    const float* brow = b + dq * 4;
    float4 val;
    val.x = wrow[0] + brow[0];
    val.y = wrow[1] + brow[1];
    val.z = wrow[2] + brow[2];
    val.w = wrow[3] + brow[3];

    float4* base = out + (size_t)pair * ROW_F4 + dq;
    // 32 u-rows per chunk, 16 covered per k-step -> 2 independent stores.
    #pragma unroll
    for (int k = 0; k < U_PER_CHUNK / 16; k++) {
        __stcs(&base[(size_t)(u0 + k * 16) * DQ], val);
    }
}

extern "C" void kernel_launch(void* const* d_in, const int* in_sizes, int n_in,
                              void* d_out, int out_size) {
    const int*   GE = (const int*)d_in[0];     // [V, G, 1] int32
    const float* W  = (const float*)d_in[1];   // [3, D]
    const float* b  = (const float*)d_in[2];   // [D]
    float4* out = (float4*)d_out;

    gembedding_broadcast_kernel<<<NUM_CTAS, 256>>>(GE, W, b, out);
}